// round 2
// baseline (speedup 1.0000x reference)
#include <cuda_runtime.h>
#include <math_constants.h>

#define PRE   1024
#define POSTN 1024
#define BATCH 32
#define NBK   64        // coarse time buckets over [0,2), width 1/32
#define BCAP  128       // max events handled per bucket (Poisson(32) -> safe)
#define NTH   256

// Transposed copies of delays/weights: [post][pre], coalesced for the main kernel.
__device__ float g_dT[POSTN * PRE];
__device__ float g_wT[POSTN * PRE];

// ---------------------------------------------------------------------------
// Transpose weights [PRE][POST] and delays [PRE][POST] -> [POST][PRE]
// ---------------------------------------------------------------------------
__global__ void transpose_kernel(const float* __restrict__ W,
                                 const float* __restrict__ D)
{
    __shared__ float tw[32][33];
    __shared__ float td[32][33];
    int x  = blockIdx.x * 32 + threadIdx.x;   // post (input col)
    int y0 = blockIdx.y * 32;                 // pre  (input row base)
#pragma unroll
    for (int j = 0; j < 32; j += 8) {
        tw[threadIdx.y + j][threadIdx.x] = W[(size_t)(y0 + threadIdx.y + j) * POSTN + x];
        td[threadIdx.y + j][threadIdx.x] = D[(size_t)(y0 + threadIdx.y + j) * POSTN + x];
    }
    __syncthreads();
    int xo  = blockIdx.y * 32 + threadIdx.x;  // pre (output col)
    int yo0 = blockIdx.x * 32;                // post (output row base)
#pragma unroll
    for (int j = 0; j < 32; j += 8) {
        g_wT[(size_t)(yo0 + threadIdx.y + j) * PRE + xo] = tw[threadIdx.x][threadIdx.y + j];
        g_dT[(size_t)(yo0 + threadIdx.y + j) * PRE + xo] = td[threadIdx.x][threadIdx.y + j];
    }
}

// ---------------------------------------------------------------------------
// Main kernel: one block per (batch, post).
// Phase A (all 256 threads): compute events, 64-bucket counting scatter.
// Phase B (one warp, bid&7): walk buckets in time order, stable rank-sort each
//   bucket, prefix-scan, evaluate candidates, STOP at first valid crossing
//   (provably the global min). "Pending" candidates that overshoot the bucket
//   edge are validated against the next nonempty bucket's earliest event.
// ---------------------------------------------------------------------------
__global__ __launch_bounds__(NTH)
void equaltime_kernel(const float* __restrict__ spikes,
                      const float* __restrict__ thresholds,
                      float* __restrict__ out)
{
    __shared__ int    offs[NBK + 1];
    __shared__ float2 ev[PRE];     // (t, w) scattered by bucket
    __shared__ int    eix[PRE];    // original pre index (stable tie-break)
    __shared__ float2 srt[BCAP];   // sorted events of current bucket

    const int tid  = threadIdx.x;
    const int bid  = blockIdx.x;
    const int post = bid >> 5;     // 32 consecutive blocks share a post column
    const int b    = bid & 31;
    const int lane = tid & 31;
    const int wid  = tid >> 5;
    const int pw   = bid & 7;      // processing warp: spread across SMSPs

    const float* dT = g_dT + (size_t)post * PRE;
    const float* wT = g_wT + (size_t)post * PRE;
    const float* sp = spikes + (size_t)b * PRE;

    if (tid <= NBK) offs[tid] = 0;

    // ---- Phase A: compute events (vectorized), histogram, scan, scatter ----
    const int i0 = tid * 4;
    float4 s4 = *reinterpret_cast<const float4*>(sp + i0);
    float4 d4 = *reinterpret_cast<const float4*>(dT + i0);
    float4 w4 = *reinterpret_cast<const float4*>(wT + i0);
    float tv[4] = { s4.x + d4.x, s4.y + d4.y, s4.z + d4.z, s4.w + d4.w };
    float wv[4] = { w4.x, w4.y, w4.z, w4.w };
    int   bk[4];
#pragma unroll
    for (int q = 0; q < 4; q++) {
        int bb = (int)(tv[q] * 32.0f);       // t in [0,2) -> bucket 0..63
        bk[q] = max(0, min(bb, NBK - 1));
    }
    __syncthreads();

#pragma unroll
    for (int q = 0; q < 4; q++) atomicAdd(&offs[bk[q] + 1], 1);
    __syncthreads();

    // inclusive scan over 64 bucket counts (2 warps)
    if (tid < NBK) {
        int v = offs[tid + 1];
#pragma unroll
        for (int o = 1; o < 32; o <<= 1) {
            int n = __shfl_up_sync(0xffffffffu, v, o);
            if (lane >= o) v += n;
        }
        offs[tid + 1] = v;
    }
    __syncthreads();
    if (tid >= 32 && tid < 64) offs[tid + 1] += offs[32];
    __syncthreads();

    // scatter: offs[j] is bucket-j start cursor; after scatter it equals end_j
#pragma unroll
    for (int q = 0; q < 4; q++) {
        int pos  = atomicAdd(&offs[bk[q]], 1);
        ev[pos]  = make_float2(tv[q], wv[q]);
        eix[pos] = i0 + q;
    }
    __syncthreads();

    // ---- Phase B: only the processing warp continues ----
    if (wid != pw) return;

    const float theta = thresholds[post];
    float cumw = 0.f, cumwt = 0.f;
    float pend = CUDART_INF_F;   // pending candidate awaiting next event time
    float res  = CUDART_INF_F;

    int lo = 0;
    for (int j = 0; j < NBK; j++) {
        const int hi = offs[j];          // end of bucket j (post-scatter)
        const int n  = hi - lo;
        if (n > 0) {
            // --- load my (<=4) events and compute stable ranks ---
            float et[4], ew2[4];
            int   ei[4], rk[4];
#pragma unroll
            for (int r = 0; r < 4; r++) {
                int p = lo + lane + 32 * r;
                if (p < hi) {
                    float2 e = ev[p];
                    et[r] = e.x; ew2[r] = e.y; ei[r] = eix[p];
                } else {
                    et[r] = CUDART_INF_F; ew2[r] = 0.f; ei[r] = 0x7fffffff;
                }
                rk[r] = 0;
            }
#pragma unroll
            for (int r2 = 0; r2 < 4; r2++) {
                int rem = n - r2 * 32;
                if (rem > 0) {
                    int iters = min(rem, 32);
                    for (int s2 = 0; s2 < iters; s2++) {
                        float tb = __shfl_sync(0xffffffffu, et[r2], s2);
                        int   ib = __shfl_sync(0xffffffffu, ei[r2], s2);
#pragma unroll
                        for (int q = 0; q < 4; q++) {
                            if (lo + lane + 32 * q < hi)
                                rk[q] += (tb < et[q]) || (tb == et[q] && ib < ei[q]);
                        }
                    }
                }
            }
            // --- write sorted bucket into srt ---
#pragma unroll
            for (int q = 0; q < 4; q++)
                if (lo + lane + 32 * q < hi)
                    srt[rk[q]] = make_float2(et[q], ew2[q]);
            __syncwarp();

            // --- resolve pending candidate against earliest event here ---
            float t_f = srt[0].x;
            if (pend <= t_f) { res = pend; break; }
            pend = CUDART_INF_F;

            // --- scan + candidate eval, 32 events per chunk, in order ---
            const float edge = (float)(j + 1) * 0.03125f;  // bucket upper edge
            bool found = false;
            for (int c = 0; c < n && !found; c += 32) {
                int  k  = c + lane;
                bool on = (k < n);
                float tk = on ? srt[k].x : 0.f;
                float wk = on ? srt[k].y : 0.f;
                float sw = wk, swt = wk * tk;
#pragma unroll
                for (int o = 1; o < 32; o <<= 1) {
                    float aw  = __shfl_up_sync(0xffffffffu, sw,  o);
                    float awt = __shfl_up_sync(0xffffffffu, swt, o);
                    if (lane >= o) { sw += aw; swt += awt; }
                }
                float CW  = cumw  + sw;
                float CWT = cumwt + swt;
                float tmp = (CW > 0.f) ? (theta + CWT) / CW : CUDART_INF_F;
                bool  last_all = (k == n - 1);
                float tn = last_all ? edge : (on ? srt[k + 1].x : 0.f);
                bool  valid = on && (CW > 0.f) && (tmp >= tk) && (tmp <= tn);
                unsigned vb = __ballot_sync(0xffffffffu, valid);
                if (vb) {
                    int fl = __ffs(vb) - 1;      // earliest window -> global min
                    res = __shfl_sync(0xffffffffu, tmp, fl);
                    found = true;
                }
                int lastl = min(31, n - 1 - c);
                cumw  = __shfl_sync(0xffffffffu, CW,  lastl);
                cumwt = __shfl_sync(0xffffffffu, CWT, lastl);
            }
            if (found) break;

            // --- create pending from the bucket's last event if it overshoots ---
            {
                float t_last = srt[n - 1].x;
                float tmpP = (cumw > 0.f) ? (theta + cumwt) / cumw : CUDART_INF_F;
                if (cumw > 0.f && tmpP >= t_last && tmpP > edge) pend = tmpP;
            }
        }
        lo = hi;
    }

    // a surviving pending was created by the LAST event overall -> always valid
    if (res == CUDART_INF_F && pend < CUDART_INF_F) res = pend;

    if (lane == 0) out[(size_t)b * POSTN + post] = res;
}

// ---------------------------------------------------------------------------
extern "C" void kernel_launch(void* const* d_in, const int* in_sizes, int n_in,
                              void* d_out, int out_size)
{
    const float* spikes  = (const float*)d_in[0];  // [32, 1024]
    const float* weights = (const float*)d_in[1];  // [1024, 1024]
    const float* delays  = (const float*)d_in[2];  // [1024, 1024]
    const float* thr     = (const float*)d_in[3];  // [1024]
    float* out = (float*)d_out;                    // [32, 1024]

    dim3 tb(32, 8);
    dim3 tg(POSTN / 32, PRE / 32);
    transpose_kernel<<<tg, tb>>>(weights, delays);

    equaltime_kernel<<<BATCH * POSTN, NTH>>>(spikes, thr, out);
}

// round 3
// speedup vs baseline: 2.2145x; 2.2145x over previous
#include <cuda_runtime.h>
#include <math_constants.h>

#define PRE    1024
#define POSTN  1024
#define BATCH  32
#define NBK    64          // coarse time buckets over [0,2)
#define WIDTH  0.03125f    // bucket width = 2/64
#define CAP    128         // detail-bucket capacity (avg ~16, max-density avg 32)
#define NTH    256
#define FULLM  0xffffffffu

// Transposed copies of delays/weights: [post][pre], coalesced for the main kernel.
__device__ float g_dT[POSTN * PRE];
__device__ float g_wT[POSTN * PRE];

// ---------------------------------------------------------------------------
__global__ void transpose_kernel(const float* __restrict__ W,
                                 const float* __restrict__ D)
{
    __shared__ float tw[32][33];
    __shared__ float td[32][33];
    int x  = blockIdx.x * 32 + threadIdx.x;
    int y0 = blockIdx.y * 32;
#pragma unroll
    for (int j = 0; j < 32; j += 8) {
        tw[threadIdx.y + j][threadIdx.x] = W[(size_t)(y0 + threadIdx.y + j) * POSTN + x];
        td[threadIdx.y + j][threadIdx.x] = D[(size_t)(y0 + threadIdx.y + j) * POSTN + x];
    }
    __syncthreads();
    int xo  = blockIdx.y * 32 + threadIdx.x;
    int yo0 = blockIdx.x * 32;
#pragma unroll
    for (int j = 0; j < 32; j += 8) {
        g_wT[(size_t)(yo0 + threadIdx.y + j) * PRE + xo] = tw[threadIdx.x][threadIdx.y + j];
        g_dT[(size_t)(yo0 + threadIdx.y + j) * PRE + xo] = td[threadIdx.x][threadIdx.y + j];
    }
}

// ---------------------------------------------------------------------------
// One block per (batch, post). Level-crossing search on V(t)=cumw*t-cumwt.
// ---------------------------------------------------------------------------
__global__ __launch_bounds__(NTH)
void equaltime_kernel(const float* __restrict__ spikes,
                      const float* __restrict__ thresholds,
                      float* __restrict__ out)
{
    __shared__ float sW[NBK], sWT[NBK], sWp[NBK];   // per-bucket sums
    __shared__ float scW[NBK], scWT[NBK];           // exclusive prefixes
    __shared__ int   sflag[NBK];                    // flagged bucket list
    __shared__ int   snflag;
    __shared__ float sTot[2];
    __shared__ float bufT[CAP], bufW[CAP];
    __shared__ float srtT[CAP], srtW[CAP];
    __shared__ int   scnt;
    __shared__ int   sdone;
    __shared__ float sres;

    const int tid  = threadIdx.x;
    const int bid  = blockIdx.x;
    const int post = bid >> 5;
    const int b    = bid & 31;
    const int lane = tid & 31;
    const int wid  = tid >> 5;

    const float theta = thresholds[post];
    const float* dT = g_dT + (size_t)post * PRE;
    const float* wT = g_wT + (size_t)post * PRE;
    const float* sp = spikes + (size_t)b * PRE;

    if (tid < NBK) { sW[tid] = 0.f; sWT[tid] = 0.f; sWp[tid] = 0.f; }
    if (tid == 0)  { scnt = 0; sdone = 0; }
    __syncthreads();

    // ---- Phase A: events in registers, 3 float atomics into 64 bins ----
    const int i0 = tid * 4;
    float4 s4 = *reinterpret_cast<const float4*>(sp + i0);
    float4 d4 = *reinterpret_cast<const float4*>(dT + i0);
    float4 w4 = *reinterpret_cast<const float4*>(wT + i0);
    float tv[4] = { s4.x + d4.x, s4.y + d4.y, s4.z + d4.z, s4.w + d4.w };
    float wv[4] = { w4.x, w4.y, w4.z, w4.w };
    int   bk[4];
#pragma unroll
    for (int q = 0; q < 4; q++) {
        int bb = (int)(tv[q] * 32.0f);
        bk[q] = max(0, min(bb, NBK - 1));
        atomicAdd(&sW[bk[q]],  wv[q]);
        atomicAdd(&sWT[bk[q]], wv[q] * tv[q]);
        atomicAdd(&sWp[bk[q]], fmaxf(wv[q], 0.f));
    }
    __syncthreads();

    // ---- Warp 0: boundary scan over 64 buckets, flag candidates ----
    if (wid == 0) {
        float w0  = sW[lane],  w1  = sW[lane + 32];
        float wt0 = sWT[lane], wt1 = sWT[lane + 32];
        float a0 = w0, a1 = w1, b0 = wt0, b1 = wt1;
#pragma unroll
        for (int o = 1; o < 32; o <<= 1) {
            float u0 = __shfl_up_sync(FULLM, a0, o);
            float u1 = __shfl_up_sync(FULLM, a1, o);
            float v0 = __shfl_up_sync(FULLM, b0, o);
            float v1 = __shfl_up_sync(FULLM, b1, o);
            if (lane >= o) { a0 += u0; a1 += u1; b0 += v0; b1 += v1; }
        }
        float T0  = __shfl_sync(FULLM, a0, 31);
        float TW0 = __shfl_sync(FULLM, b0, 31);
        a1 += T0; b1 += TW0;
        float e0 = a0 - w0,  e1 = a1 - w1;    // exclusive Σw prefix
        float f0 = b0 - wt0, f1 = b1 - wt1;   // exclusive Σw*t prefix
        scW[lane] = e0;  scW[lane + 32] = e1;
        scWT[lane] = f0; scWT[lane + 32] = f1;
        if (lane == 31) { sTot[0] = a1; sTot[1] = b1; }
        float B0 = lane * WIDTH, B1 = (lane + 32) * WIDTH;
        float V0 = e0 * B0 - f0;
        float V1 = e1 * B1 - f1;
        bool fl0 = V0 + fmaxf(e0 + sWp[lane],      0.f) * WIDTH >= theta;
        bool fl1 = V1 + fmaxf(e1 + sWp[lane + 32], 0.f) * WIDTH >= theta;
        unsigned m0 = __ballot_sync(FULLM, fl0);
        unsigned m1 = __ballot_sync(FULLM, fl1);
        int n0 = __popc(m0);
        if (fl0) sflag[__popc(m0 & ((1u << lane) - 1))] = lane;
        if (fl1) sflag[n0 + __popc(m1 & ((1u << lane) - 1))] = lane + 32;
        if (lane == 0) snflag = n0 + __popc(m1);
    }
    __syncthreads();

    // ---- Candidate-bucket loop (usually 1 iteration) ----
    const int nflag = snflag;
    for (int idx = 0; idx < nflag; idx++) {
        const int j = sflag[idx];
        // all threads: compact register-resident events of bucket j
#pragma unroll
        for (int q = 0; q < 4; q++) {
            if (bk[q] == j) {
                int p = atomicAdd(&scnt, 1);
                if (p < CAP) { bufT[p] = tv[q]; bufW[p] = wv[q]; }
            }
        }
        __syncthreads();

        if (wid == 0) {
            const int n = min(scnt, CAP);
            // stable-enough rank sort (position tie-break; tie order provably irrelevant)
            float rt[4], rw[4];
            int   rk[4];
#pragma unroll
            for (int r = 0; r < 4; r++) {
                int p = lane + 32 * r;
                bool on = (p < n);
                rt[r] = on ? bufT[p] : CUDART_INF_F;
                rw[r] = on ? bufW[p] : 0.f;
                rk[r] = 0;
            }
#pragma unroll
            for (int r2 = 0; r2 < 4; r2++) {
                if (r2 * 32 < n) {
                    int m = min(n - r2 * 32, 32);
                    for (int s = 0; s < m; s++) {
                        float tb = __shfl_sync(FULLM, rt[r2], s);
                        int   pb = r2 * 32 + s;
#pragma unroll
                        for (int q = 0; q < 4; q++) {
                            int myp = lane + 32 * q;
                            if (myp < n)
                                rk[q] += (tb < rt[q]) || (tb == rt[q] && pb < myp);
                        }
                    }
                }
            }
#pragma unroll
            for (int q = 0; q < 4; q++)
                if (lane + 32 * q < n) { srtT[rk[q]] = rt[q]; srtW[rk[q]] = rw[q]; }
            __syncwarp();

            float cw = scW[j], cwt = scWT[j];
            bool  found = false;
            float tmp = 0.f;
            for (int c = 0; c < n && !found; c += 32) {
                int  k  = c + lane;
                bool on = (k < n);
                float tk = on ? srtT[k] : 0.f;
                float wk = on ? srtW[k] : 0.f;
                float swi = wk, swti = wk * tk;
#pragma unroll
                for (int o = 1; o < 32; o <<= 1) {
                    float u = __shfl_up_sync(FULLM, swi,  o);
                    float v = __shfl_up_sync(FULLM, swti, o);
                    if (lane >= o) { swi += u; swti += v; }
                }
                float CWp  = cw  + swi  - wk;        // cum before event k
                float CWTp = cwt + swti - wk * tk;
                float V    = CWp * tk - CWTp;
                bool cross = on && (V >= theta) && (CWp > 0.f);
                unsigned cb = __ballot_sync(FULLM, cross);
                if (cb) {
                    int f = __ffs(cb) - 1;
                    float cand = (theta + CWTp) / CWp;
                    tmp = __shfl_sync(FULLM, cand, f);
                    found = true;
                } else {
                    int lastl = min(31, n - 1 - c);
                    cw  += __shfl_sync(FULLM, swi,  lastl);
                    cwt += __shfl_sync(FULLM, swti, lastl);
                }
            }
            if (!found && cw > 0.f) {
                float Bend = (float)(j + 1) * WIDTH;
                if (cw * Bend - cwt >= theta) {      // crossing after last event, in bucket
                    tmp = (theta + cwt) / cw;
                    found = true;
                }
            }
            if (found && lane == 0) { sres = tmp; sdone = 1; }
        }
        __syncthreads();
        if (sdone) break;
        if (tid == 0) scnt = 0;
        __syncthreads();
    }

    if (tid == 0) {
        float r;
        if (sdone) r = sres;
        else {
            float cw = sTot[0], cwt = sTot[1];
            r = (cw > 0.f) ? (theta + cwt) / cw : CUDART_INF_F;  // final open window
        }
        out[(size_t)b * POSTN + post] = r;
    }
}

// ---------------------------------------------------------------------------
extern "C" void kernel_launch(void* const* d_in, const int* in_sizes, int n_in,
                              void* d_out, int out_size)
{
    const float* spikes  = (const float*)d_in[0];  // [32, 1024]
    const float* weights = (const float*)d_in[1];  // [1024, 1024]
    const float* delays  = (const float*)d_in[2];  // [1024, 1024]
    const float* thr     = (const float*)d_in[3];  // [1024]
    float* out = (float*)d_out;                    // [32, 1024]

    dim3 tb(32, 8);
    dim3 tg(POSTN / 32, PRE / 32);
    transpose_kernel<<<tg, tb>>>(weights, delays);

    equaltime_kernel<<<BATCH * POSTN, NTH>>>(spikes, thr, out);
}